// round 1
// baseline (speedup 1.0000x reference)
#include <cuda_runtime.h>
#include <cstdint>
#include <cstdio>
#include <math.h>

// Problem constants
#define Tn   4096
#define Hn   1024
#define FH   4096          // 4*H
#define NCTA 128           // CTAs in recurrent kernel (<= 148 SMs, all co-resident)
#define UPB  8             // hidden units per CTA (8 warps, 1 unit/warp)

// ---------------------------------------------------------------------------
// Scratch (device globals -- no allocation allowed)
// ---------------------------------------------------------------------------
__device__ float    d_G[(size_t)Tn * FH];       // 64 MB: gate preactivations (reused by both layers)
__device__ float    d_h0seq[(size_t)Tn * Hn];   // 16 MB: layer-0 hidden sequence
__device__ float    d_hbuf[2 * Hn];             // double-buffered h_{t-1}
__device__ unsigned d_bar[2 * Tn];              // per-step barrier counters (one slot per layer)

// ---------------------------------------------------------------------------
// GEMM: C[M][N] = gather(A)[M][K] * B[N][K]^T + b1[N] + b2[N]
// Both A and B are K-major (row-major, K contiguous) -> NT GEMM.
// Tiles: 128x128, KC=16, 8x8 microtile per thread, k-major smem with +4 pad.
// ---------------------------------------------------------------------------
#define BM 128
#define BN 128
#define KC 16
#define BMP (BM + 4)
#define BNP (BN + 4)

__global__ __launch_bounds__(256, 1)
void gemm_nt_bias(const float* __restrict__ A, const int* __restrict__ aidx,
                  const float* __restrict__ B,
                  const float* __restrict__ b1, const float* __restrict__ b2,
                  float* __restrict__ C, int N, int K)
{
    __shared__ float sA[KC][BMP];
    __shared__ float sB[KC][BNP];

    const int nbx = N / BN;
    const int bx  = blockIdx.x % nbx;
    const int by  = blockIdx.x / nbx;
    const int tid = threadIdx.x;
    const int tx  = tid & 15;
    const int ty  = tid >> 4;
    const int row0 = by * BM, col0 = bx * BN;

    // load mapping: each thread moves 2 float4 per matrix per K-chunk
    const int lr = tid >> 2;          // 0..63
    const int ks = (tid & 3) << 2;    // 0,4,8,12

    size_t aoff0, aoff1;
    {
        int r0 = row0 + lr, r1 = r0 + 64;
        int g0 = aidx ? aidx[r0] : r0;
        int g1 = aidx ? aidx[r1] : r1;
        aoff0 = (size_t)g0 * K + ks;
        aoff1 = (size_t)g1 * K + ks;
    }
    size_t boff0 = (size_t)(col0 + lr) * K + ks;
    size_t boff1 = boff0 + (size_t)64 * K;

    float acc[8][8];
    #pragma unroll
    for (int i = 0; i < 8; i++)
        #pragma unroll
        for (int j = 0; j < 8; j++) acc[i][j] = 0.f;

    #pragma unroll 1
    for (int k0 = 0; k0 < K; k0 += KC) {
        float4 va0 = *(const float4*)(A + aoff0 + k0);
        float4 va1 = *(const float4*)(A + aoff1 + k0);
        float4 vb0 = *(const float4*)(B + boff0 + k0);
        float4 vb1 = *(const float4*)(B + boff1 + k0);
        __syncthreads();   // previous chunk's compute done
        sA[ks+0][lr]    = va0.x; sA[ks+1][lr]    = va0.y; sA[ks+2][lr]    = va0.z; sA[ks+3][lr]    = va0.w;
        sA[ks+0][lr+64] = va1.x; sA[ks+1][lr+64] = va1.y; sA[ks+2][lr+64] = va1.z; sA[ks+3][lr+64] = va1.w;
        sB[ks+0][lr]    = vb0.x; sB[ks+1][lr]    = vb0.y; sB[ks+2][lr]    = vb0.z; sB[ks+3][lr]    = vb0.w;
        sB[ks+0][lr+64] = vb1.x; sB[ks+1][lr+64] = vb1.y; sB[ks+2][lr+64] = vb1.z; sB[ks+3][lr+64] = vb1.w;
        __syncthreads();
        #pragma unroll
        for (int kk = 0; kk < KC; kk++) {
            float4 a0v = *(const float4*)&sA[kk][ty * 8];
            float4 a1v = *(const float4*)&sA[kk][ty * 8 + 4];
            float4 b0v = *(const float4*)&sB[kk][tx * 8];
            float4 b1v = *(const float4*)&sB[kk][tx * 8 + 4];
            float ar[8] = {a0v.x, a0v.y, a0v.z, a0v.w, a1v.x, a1v.y, a1v.z, a1v.w};
            float br[8] = {b0v.x, b0v.y, b0v.z, b0v.w, b1v.x, b1v.y, b1v.z, b1v.w};
            #pragma unroll
            for (int i = 0; i < 8; i++)
                #pragma unroll
                for (int j = 0; j < 8; j++)
                    acc[i][j] += ar[i] * br[j];
        }
    }

    // epilogue with fused bias sum
    float bsum[8];
    #pragma unroll
    for (int j = 0; j < 8; j++) {
        int col = col0 + tx * 8 + j;
        bsum[j] = b1[col] + b2[col];
    }
    #pragma unroll
    for (int i = 0; i < 8; i++) {
        int row = row0 + ty * 8 + i;
        float4 o0 = make_float4(acc[i][0] + bsum[0], acc[i][1] + bsum[1],
                                acc[i][2] + bsum[2], acc[i][3] + bsum[3]);
        float4 o1 = make_float4(acc[i][4] + bsum[4], acc[i][5] + bsum[5],
                                acc[i][6] + bsum[6], acc[i][7] + bsum[7]);
        float* crow = C + (size_t)row * N + col0 + tx * 8;
        *(float4*)(crow)     = o0;
        *(float4*)(crow + 4) = o1;
    }
}

// ---------------------------------------------------------------------------
// Recurrent LSTM layer: persistent kernel, weights register-resident.
// grid = NCTA (128), block = 256 (8 warps). Warp w of block b owns hidden
// unit u = b*8+w and its 4 gate rows (i,f,g,o) of W_hh. Per step: stage h
// into smem (L2-coherent loads), 128 FMAs/lane, butterfly reduce, cell
// update, write h, per-step atomic grid barrier.
// ---------------------------------------------------------------------------
__device__ __forceinline__ float sigf(float x) { return 1.f / (1.f + expf(-x)); }

__global__ __launch_bounds__(256, 1)
void lstm_layer_kernel(const float* __restrict__ Whh,   // [4H][H]
                       const float* __restrict__ G,     // [T][4H] (= W_ih@x + b_ih + b_hh)
                       float* __restrict__ seq,         // [T][H] per-step h output
                       float* __restrict__ hT, float* __restrict__ cT,
                       unsigned* __restrict__ bar)
{
    const int tid  = threadIdx.x;
    const int warp = tid >> 5;
    const int lane = tid & 31;
    const int unit = blockIdx.x * UPB + warp;

    // Register-resident weights: lane covers elements i*128 + lane*4 + c
    float4 w[4][8];
    #pragma unroll
    for (int g = 0; g < 4; g++) {
        const float4* wr = (const float4*)(Whh + (size_t)(g * Hn + unit) * Hn);
        #pragma unroll
        for (int i = 0; i < 8; i++)
            w[g][i] = wr[i * 32 + lane];
    }

    __shared__ float4 sh[Hn / 4];   // staged h_{t-1}

    float c = 0.f;
    const float4* hb4 = (const float4*)d_hbuf;

    #pragma unroll 1
    for (int t = 0; t < Tn; t++) {
        // prefetch gate preactivations (independent of barrier/h)
        const float* gp = G + (size_t)t * FH + unit;
        float gv0 = gp[0];
        float gv1 = gp[Hn];
        float gv2 = gp[2 * Hn];
        float gv3 = gp[3 * Hn];

        float a0 = 0.f, a1 = 0.f, a2 = 0.f, a3 = 0.f;
        if (t > 0) {
            // stage h (bypass L1: written by other SMs within this launch)
            sh[tid] = __ldcg(hb4 + (t & 1) * (Hn / 4) + tid);
            __syncthreads();
            #pragma unroll
            for (int i = 0; i < 8; i++) {
                float4 hv = sh[i * 32 + lane];
                a0 += w[0][i].x * hv.x; a0 += w[0][i].y * hv.y; a0 += w[0][i].z * hv.z; a0 += w[0][i].w * hv.w;
                a1 += w[1][i].x * hv.x; a1 += w[1][i].y * hv.y; a1 += w[1][i].z * hv.z; a1 += w[1][i].w * hv.w;
                a2 += w[2][i].x * hv.x; a2 += w[2][i].y * hv.y; a2 += w[2][i].z * hv.z; a2 += w[2][i].w * hv.w;
                a3 += w[3][i].x * hv.x; a3 += w[3][i].y * hv.y; a3 += w[3][i].z * hv.z; a3 += w[3][i].w * hv.w;
            }
        }

        // full-warp butterfly reduce (all lanes end with totals)
        #pragma unroll
        for (int off = 16; off; off >>= 1) {
            a0 += __shfl_xor_sync(0xFFFFFFFFu, a0, off);
            a1 += __shfl_xor_sync(0xFFFFFFFFu, a1, off);
            a2 += __shfl_xor_sync(0xFFFFFFFFu, a2, off);
            a3 += __shfl_xor_sync(0xFFFFFFFFu, a3, off);
        }

        float ig = sigf(gv0 + a0);
        float fg = sigf(gv1 + a1);
        float gg = tanhf(gv2 + a2);
        float og = sigf(gv3 + a3);
        c = fg * c + ig * gg;
        float h = og * tanhf(c);

        if (lane == 0) {
            d_hbuf[((t + 1) & 1) * Hn + unit] = h;
            seq[(size_t)t * Hn + unit] = h;
            if (t == Tn - 1) { hT[unit] = h; cT[unit] = c; }
            __threadfence();   // make writes device-visible before barrier arrive
        }

        // grid barrier (per-step counter; all 128 CTAs co-resident)
        __syncthreads();
        if (tid == 0) {
            atomicAdd(&bar[t], 1u);
            while (*((volatile unsigned*)&bar[t]) < (unsigned)NCTA) { }
            __threadfence();
        }
        __syncthreads();
    }
}

// ---------------------------------------------------------------------------
// Launch: GEMM0 (embedding-gather fused) -> layer0 recurrence -> GEMM1 ->
//         layer1 recurrence. All graph-capturable, no allocation.
// ---------------------------------------------------------------------------
extern "C" void kernel_launch(void* const* d_in, const int* in_sizes, int n_in,
                              void* d_out, int out_size)
{
    const int*   tok = (const int*)d_in[0];
    const float* emb = (const float*)d_in[1];
    const float* Wih = (const float*)d_in[2];
    const float* Whh = (const float*)d_in[3];
    const float* bih = (const float*)d_in[4];
    const float* bhh = (const float*)d_in[5];
    float* out = (float*)d_out;

    float *G, *h0seq;
    unsigned* bar;
    cudaGetSymbolAddress((void**)&G,     d_G);
    cudaGetSymbolAddress((void**)&h0seq, d_h0seq);
    cudaGetSymbolAddress((void**)&bar,   d_bar);

    // zero per-step barrier counters (deterministic across graph replays)
    cudaMemsetAsync(bar, 0, sizeof(unsigned) * 2 * Tn, 0);

    float* outs = out;                        // [T][H]
    float* hTp  = out + (size_t)Tn * Hn;      // [L][H]
    float* cTp  = hTp + 2 * Hn;               // [L][H]

    const int gemm_grid = (Tn / BM) * (FH / BN);   // 32*32 = 1024

    // Layer 0 input projection: G = emb[tok] @ W_ih0^T + b_ih0 + b_hh0
    gemm_nt_bias<<<gemm_grid, 256>>>(emb, tok, Wih, bih, bhh, G, FH, Hn);

    // Layer 0 recurrence
    lstm_layer_kernel<<<NCTA, 256>>>(Whh, G, h0seq, hTp, cTp, bar);

    // Layer 1 input projection: G = h0seq @ W_ih1^T + b_ih1 + b_hh1
    gemm_nt_bias<<<gemm_grid, 256>>>(h0seq, nullptr, Wih + (size_t)FH * Hn,
                                     bih + FH, bhh + FH, G, FH, Hn);

    // Layer 1 recurrence (writes outs + final states)
    lstm_layer_kernel<<<NCTA, 256>>>(Whh + (size_t)FH * Hn, G, outs,
                                     hTp + Hn, cTp + Hn, bar + Tn);
}